// round 14
// baseline (speedup 1.0000x reference)
#include <cuda_runtime.h>
#include <cuda_fp16.h>
#include <math.h>

#define N_NODES 100000
#define N_FEATS 2048
#define HID 64
#define NLAB 40
#define N_SEG (2 * N_NODES)
#define MAX_NNZ 2500000
#define MAX_NE  1700000
#define FCAP 6144            // staged feat entries per 32-row block (24 KB)
#define ECAP 3072            // staged edge entries per 32-row block (24 KB)

// ---- scratch (static: no allocations; zero-init at load) ----
__device__ __align__(16) __half2 g_W1h[N_FEATS * HID / 2];   // fp16 W1 (256 KB)
__device__ __align__(16) __half2 g_h1h[N_NODES * HID / 2];   // h1 fp16 (12.8 MB)
__device__ __align__(16) __half2 g_h2h[N_NODES * HID / 2];   // h2 fp16, relu'ed
__device__ __align__(16) __half2 g_z1h[N_NODES * NLAB / 2];  // z1 fp16 (8 MB)
__device__ int g_cnt[N_SEG];        // invariant: all-zero at kernel_launch entry
__device__ int g_start[N_SEG];
__device__ int g_cursor[N_SEG];
__device__ int gTotF, gTotE;        // scan bases; reset by k_dense each call
__device__ unsigned g_fbuf[MAX_NNZ];                  // (col<<16)|fp16(val), by row
__device__ __align__(8) int2 g_ebuf[MAX_NE];          // (col, w bits), by row

__device__ __forceinline__ int clamp_i(int i, int n) {
    i = i < 0 ? 0 : i;
    return i >= n ? n - 1 : i;
}

__device__ __forceinline__ void acc8(float4& a, float4& b, float s, uint4 u) {
    float2 lx = __half22float2(*(__half2*)&u.x);
    float2 ly = __half22float2(*(__half2*)&u.y);
    float2 lz = __half22float2(*(__half2*)&u.z);
    float2 lw = __half22float2(*(__half2*)&u.w);
    a.x += s * lx.x; a.y += s * lx.y; a.z += s * ly.x; a.w += s * ly.y;
    b.x += s * lz.x; b.y += s * lz.y; b.z += s * lw.x; b.w += s * lw.y;
}
__device__ __forceinline__ uint4 f8_to_h8(float4 a, float4 b) {
    __half2 p = __floats2half2_rn(a.x, a.y), q = __floats2half2_rn(a.z, a.w);
    __half2 r = __floats2half2_rn(b.x, b.y), s = __floats2half2_rn(b.z, b.w);
    uint4 u;
    u.x = *(unsigned*)&p; u.y = *(unsigned*)&q;
    u.z = *(unsigned*)&r; u.w = *(unsigned*)&s;
    return u;
}
// fp16 HFMA2 accumulate: acc += v2 * u  (4 HFMA2, no unpack)
__device__ __forceinline__ void hacc8(uint4& a, __half2 v2, uint4 u) {
    *(__half2*)&a.x = __hfma2(v2, *(__half2*)&u.x, *(__half2*)&a.x);
    *(__half2*)&a.y = __hfma2(v2, *(__half2*)&u.y, *(__half2*)&a.y);
    *(__half2*)&a.z = __hfma2(v2, *(__half2*)&u.z, *(__half2*)&a.z);
    *(__half2*)&a.w = __hfma2(v2, *(__half2*)&u.w, *(__half2*)&a.w);
}

// ---------------- build: histogram (+ W1 fp16 convert folded in) ----------------
__global__ void k_hist(const int* __restrict__ fi, int nnz,
                       const int* __restrict__ ei, int ne,
                       const float* __restrict__ W1) {
    int e = blockIdx.x * blockDim.x + threadIdx.x;
    if (e < N_FEATS * HID / 2) {
        float2 f = __ldg((const float2*)W1 + e);
        g_W1h[e] = __floats2half2_rn(f.x, f.y);
    }
    if (e < nnz) {
        atomicAdd(&g_cnt[clamp_i(__ldg(&fi[e]), N_NODES)], 1);
    } else if (e < nnz + ne) {
        int t = e - nnz;
        atomicAdd(&g_cnt[N_NODES + clamp_i(__ldg(&ei[t]), N_NODES)], 1);
    }
}

// ---------------- single-kernel scan: 250 blocks x 800 (125 feat | 125 edge) --------
// NOTE: block bases via atomicAdd -> starts are contiguous WITHIN each 800-row
// scan block. 32 | 800, so every 32-row SpMM block's entries are contiguous.
__global__ __launch_bounds__(800) void k_scan() {
    int tid = threadIdx.x;
    int bid = blockIdx.x;
    int i = bid * 800 + tid;                 // 250*800 = 200000 = N_SEG exactly
    int v = g_cnt[i];
    int lane = tid & 31, wid = tid >> 5;
    int x = v;
#pragma unroll
    for (int o = 1; o < 32; o <<= 1) {
        int y = __shfl_up_sync(0xFFFFFFFFu, x, o);
        if (lane >= o) x += y;
    }
    __shared__ int ws[25];
    __shared__ int sbase;
    if (lane == 31) ws[wid] = x;
    __syncthreads();
    if (tid < 32) {
        int s = (tid < 25) ? ws[tid] : 0;
#pragma unroll
        for (int o = 1; o < 32; o <<= 1) {
            int y = __shfl_up_sync(0xFFFFFFFFu, s, o);
            if (tid >= o) s += y;
        }
        if (tid < 25) ws[tid] = s;           // inclusive scan of warp sums
        if (tid == 24) sbase = atomicAdd((bid >= 125) ? &gTotE : &gTotF, s);
    }
    __syncthreads();
    int incl = x + (wid ? ws[wid - 1] : 0);
    int st = sbase + incl - v;               // exclusive start (fbuf- or ebuf-relative)
    g_start[i] = st;
    g_cursor[i] = st;
}

// ---------------- scatter: features (packed 4B) then edges (8B) ----------------
__global__ void k_scat(const int* __restrict__ fi, const float* __restrict__ fv, int nnz,
                       const int* __restrict__ ei, const float* __restrict__ ew, int ne) {
    int e = blockIdx.x * blockDim.x + threadIdx.x;
    if (e < nnz) {
        int row = clamp_i(__ldg(&fi[e]), N_NODES);
        int col = clamp_i(__ldg(&fi[nnz + e]), N_FEATS);
        __half hv = __float2half_rn(__ldg(&fv[e]));
        int pos = atomicAdd(&g_cursor[row], 1);
        g_fbuf[pos] = ((unsigned)col << 16) | (unsigned)*(unsigned short*)&hv;
    } else if (e < nnz + ne) {
        int t = e - nnz;
        int row = clamp_i(__ldg(&ei[t]), N_NODES);
        int col = clamp_i(__ldg(&ei[ne + t]), N_NODES);
        float wv = __ldg(&ew[t]);
        int pos = atomicAdd(&g_cursor[N_NODES + row], 1);    // ebuf-relative
        g_ebuf[pos] = make_int2(col, __float_as_int(wv));
    }
}

// ---------------- gather SpMMs: entry staging in smem, 8 lanes x uint4 per row --------
// h1[row] = b1 + sum_i val_i * W1[col_i, :]   (fp16 HFMA2 accumulation)
__global__ __launch_bounds__(256) void k_feat_csr(const float* __restrict__ b1) {
    __shared__ unsigned sent[FCAP];
    int tid = threadIdx.x;
    int row0 = blockIdx.x * 32;              // 3125*32 = 100000 exactly
    int row = row0 + (tid >> 3);
    int q = tid & 7;
    int s = g_start[row];
    int n = g_cnt[row];
    int sBase = g_start[row0];
    int span = g_start[row0 + 31] + g_cnt[row0 + 31] - sBase;
    bool staged = (span <= FCAP);
    if (staged)
        for (int i = tid; i < span; i += 256) sent[i] = __ldg(&g_fbuf[sBase + i]);
    __syncthreads();
    if (q == 0) g_cnt[row] = 0;              // restore invariant (all reads done)

    uint4 acc = f8_to_h8(__ldg((const float4*)b1 + q * 2),
                         __ldg((const float4*)b1 + q * 2 + 1));
    const uint4* W = (const uint4*)g_W1h;    // 8 uint4 per W1 row
    int i = 0;
    if (staged) {
        const unsigned* E = sent + (s - sBase);
        for (; i + 4 <= n; i += 4) {
            unsigned p0 = E[i], p1 = E[i + 1], p2 = E[i + 2], p3 = E[i + 3];
            uint4 u0 = __ldg(W + (size_t)(p0 >> 16) * 8 + q);
            uint4 u1 = __ldg(W + (size_t)(p1 >> 16) * 8 + q);
            uint4 u2 = __ldg(W + (size_t)(p2 >> 16) * 8 + q);
            uint4 u3 = __ldg(W + (size_t)(p3 >> 16) * 8 + q);
            unsigned short b0 = (unsigned short)p0, b1s = (unsigned short)p1;
            unsigned short b2 = (unsigned short)p2, b3 = (unsigned short)p3;
            hacc8(acc, __half2half2(*(__half*)&b0), u0);
            hacc8(acc, __half2half2(*(__half*)&b1s), u1);
            hacc8(acc, __half2half2(*(__half*)&b2), u2);
            hacc8(acc, __half2half2(*(__half*)&b3), u3);
        }
        for (; i < n; i++) {
            unsigned p = E[i];
            uint4 u = __ldg(W + (size_t)(p >> 16) * 8 + q);
            unsigned short b = (unsigned short)p;
            hacc8(acc, __half2half2(*(__half*)&b), u);
        }
    } else {
        for (; i < n; i++) {
            unsigned p = __ldg(&g_fbuf[s + i]);
            uint4 u = __ldg(W + (size_t)(p >> 16) * 8 + q);
            unsigned short b = (unsigned short)p;
            hacc8(acc, __half2half2(*(__half*)&b), u);
        }
    }
    ((uint4*)g_h1h)[(size_t)row * 8 + q] = acc;
}

// h2[row] = relu( sum_i w_i * h1[col_i] )   (fp16 HFMA2 accumulation)
__global__ __launch_bounds__(256) void k_edge64_csr() {
    __shared__ int2 sent[ECAP];
    int tid = threadIdx.x;
    int row0 = blockIdx.x * 32;
    int row = row0 + (tid >> 3);
    int q = tid & 7;
    int s = g_start[N_NODES + row];
    int n = g_cnt[N_NODES + row];
    int sBase = g_start[N_NODES + row0];
    int span = g_start[N_NODES + row0 + 31] + g_cnt[N_NODES + row0 + 31] - sBase;
    bool staged = (span <= ECAP);
    if (staged)
        for (int i = tid; i < span; i += 256) sent[i] = __ldg(&g_ebuf[sBase + i]);
    __syncthreads();

    const uint4* H = (const uint4*)g_h1h;
    uint4 acc = make_uint4(0u, 0u, 0u, 0u);
    int i = 0;
    if (staged) {
        const int2* E = sent + (s - sBase);
        for (; i + 4 <= n; i += 4) {
            int2 p0 = E[i], p1 = E[i + 1], p2 = E[i + 2], p3 = E[i + 3];
            uint4 u0 = __ldg(H + (size_t)p0.x * 8 + q);
            uint4 u1 = __ldg(H + (size_t)p1.x * 8 + q);
            uint4 u2 = __ldg(H + (size_t)p2.x * 8 + q);
            uint4 u3 = __ldg(H + (size_t)p3.x * 8 + q);
            hacc8(acc, __float2half2_rn(__int_as_float(p0.y)), u0);
            hacc8(acc, __float2half2_rn(__int_as_float(p1.y)), u1);
            hacc8(acc, __float2half2_rn(__int_as_float(p2.y)), u2);
            hacc8(acc, __float2half2_rn(__int_as_float(p3.y)), u3);
        }
        for (; i < n; i++) {
            int2 p = E[i];
            uint4 u = __ldg(H + (size_t)p.x * 8 + q);
            hacc8(acc, __float2half2_rn(__int_as_float(p.y)), u);
        }
    } else {
        for (; i < n; i++) {
            int2 p = __ldg(&g_ebuf[s + i]);
            uint4 u = __ldg(H + (size_t)p.x * 8 + q);
            hacc8(acc, __float2half2_rn(__int_as_float(p.y)), u);
        }
    }
    __half2 z2 = __float2half2_rn(0.f);
    *(__half2*)&acc.x = __hmax2(*(__half2*)&acc.x, z2);
    *(__half2*)&acc.y = __hmax2(*(__half2*)&acc.y, z2);
    *(__half2*)&acc.z = __hmax2(*(__half2*)&acc.z, z2);
    *(__half2*)&acc.w = __hmax2(*(__half2*)&acc.w, z2);
    ((uint4*)g_h2h)[(size_t)row * 8 + q] = acc;
}

// ---------------- dense: z1 = h2 @ W2 + b2 (fp16 in/out, fp32 math) ----------------
#define PADK 68
__global__ __launch_bounds__(256) void k_dense(const float* __restrict__ W2,
                                               const float* __restrict__ b2) {
    if (blockIdx.x == 0 && threadIdx.x == 0) { gTotF = 0; gTotE = 0; }  // reset scan bases
    __shared__ float sW2t[NLAB * PADK];   // [j][k]
    __shared__ float sb2[NLAB];
    int tid = threadIdx.x;
    for (int i = tid; i < HID * NLAB; i += 256) {
        int k = i / NLAB, j = i - k * NLAB;
        sW2t[j * PADK + k] = W2[i];
    }
    if (tid < NLAB) sb2[tid] = b2[tid];
    __syncthreads();

    int j0 = (tid & 3) * 10;
    int n0 = (blockIdx.x * 64 + (tid >> 2)) * 4;

    float acc[4][10];
#pragma unroll
    for (int nn = 0; nn < 4; nn++)
#pragma unroll
        for (int j = 0; j < 10; j++) acc[nn][j] = sb2[j0 + j];

    const uint2* H = (const uint2*)g_h2h;     // 16 uint2 per h2 row
#pragma unroll
    for (int k4 = 0; k4 < HID; k4 += 4) {
        float4 h[4];
#pragma unroll
        for (int nn = 0; nn < 4; nn++) {
            int nd = n0 + nn;
            if (nd < N_NODES) {
                uint2 u = __ldg(H + (size_t)nd * 16 + (k4 >> 2));
                float2 a = __half22float2(*(__half2*)&u.x);
                float2 b = __half22float2(*(__half2*)&u.y);
                h[nn] = make_float4(a.x, a.y, b.x, b.y);
            } else h[nn] = make_float4(0.f, 0.f, 0.f, 0.f);
        }
#pragma unroll
        for (int j = 0; j < 10; j++) {
            float4 wv = *(const float4*)&sW2t[(j0 + j) * PADK + k4];
#pragma unroll
            for (int nn = 0; nn < 4; nn++)
                acc[nn][j] += h[nn].x * wv.x + h[nn].y * wv.y + h[nn].z * wv.z + h[nn].w * wv.w;
        }
    }
    unsigned short* Z = (unsigned short*)g_z1h;
#pragma unroll
    for (int nn = 0; nn < 4; nn++) {
        int nd = n0 + nn;
        if (nd >= N_NODES) break;
        unsigned* zp = (unsigned*)(Z + (size_t)nd * NLAB + j0);
#pragma unroll
        for (int j = 0; j < 10; j += 2) {
            __half2 hp = __floats2half2_rn(acc[nn][j], acc[nn][j + 1]);
            zp[j >> 1] = *(unsigned*)&hp;
        }
    }
}

// ---------------- final propagate + fused log-softmax (8-lane groups, 5 active) --------
__global__ __launch_bounds__(256) void k_edge40_lsm(float* __restrict__ out) {
    __shared__ int2 sent[ECAP];
    int tid = threadIdx.x;
    int row0 = blockIdx.x * 32;
    int row = row0 + (tid >> 3);
    int q = tid & 7;
    int s = g_start[N_NODES + row];
    int n = g_cnt[N_NODES + row];
    int sBase = g_start[N_NODES + row0];
    int span = g_start[N_NODES + row0 + 31] + g_cnt[N_NODES + row0 + 31] - sBase;
    bool staged = (span <= ECAP);
    if (staged)
        for (int i = tid; i < span; i += 256) sent[i] = __ldg(&g_ebuf[sBase + i]);
    __syncthreads();
    if (q == 0) g_cnt[N_NODES + row] = 0;    // restore invariant (all reads done)

    bool act = (q < 5);
    const uint4* Z = (const uint4*)g_z1h;    // 5 uint4 per z row
    float4 accA = make_float4(0.f, 0.f, 0.f, 0.f);
    float4 accB = make_float4(0.f, 0.f, 0.f, 0.f);
    int i = 0;
    if (staged) {
        const int2* E = sent + (s - sBase);
        for (; i + 4 <= n; i += 4) {
            int2 p0 = E[i], p1 = E[i + 1], p2 = E[i + 2], p3 = E[i + 3];
            if (act) {
                uint4 u0 = __ldg(Z + (size_t)p0.x * 5 + q);
                uint4 u1 = __ldg(Z + (size_t)p1.x * 5 + q);
                uint4 u2 = __ldg(Z + (size_t)p2.x * 5 + q);
                uint4 u3 = __ldg(Z + (size_t)p3.x * 5 + q);
                acc8(accA, accB, __int_as_float(p0.y), u0);
                acc8(accA, accB, __int_as_float(p1.y), u1);
                acc8(accA, accB, __int_as_float(p2.y), u2);
                acc8(accA, accB, __int_as_float(p3.y), u3);
            }
        }
        for (; i < n; i++) {
            int2 p = E[i];
            if (act) {
                uint4 u = __ldg(Z + (size_t)p.x * 5 + q);
                acc8(accA, accB, __int_as_float(p.y), u);
            }
        }
    } else {
        for (; i < n; i++) {
            int2 p = __ldg(&g_ebuf[s + i]);
            if (act) {
                uint4 u = __ldg(Z + (size_t)p.x * 5 + q);
                acc8(accA, accB, __int_as_float(p.y), u);
            }
        }
    }
    float m = act ? fmaxf(fmaxf(fmaxf(accA.x, accA.y), fmaxf(accA.z, accA.w)),
                          fmaxf(fmaxf(accB.x, accB.y), fmaxf(accB.z, accB.w))) : -1e30f;
#pragma unroll
    for (int o = 1; o < 8; o <<= 1) m = fmaxf(m, __shfl_xor_sync(0xFFFFFFFFu, m, o, 8));
    float es = act ? (expf(accA.x - m) + expf(accA.y - m) + expf(accA.z - m) + expf(accA.w - m) +
                      expf(accB.x - m) + expf(accB.y - m) + expf(accB.z - m) + expf(accB.w - m)) : 0.f;
#pragma unroll
    for (int o = 1; o < 8; o <<= 1) es += __shfl_xor_sync(0xFFFFFFFFu, es, o, 8);
    float l = m + logf(es);
    if (act) {
        float* op = out + (size_t)row * NLAB + q * 8;
        *(float4*)op = make_float4(accA.x - l, accA.y - l, accA.z - l, accA.w - l);
        *(float4*)(op + 4) = make_float4(accB.x - l, accB.y - l, accB.z - l, accB.w - l);
    }
}

extern "C" void kernel_launch(void* const* d_in, const int* in_sizes, int n_in,
                              void* d_out, int out_size) {
    // Bind inputs by element count (pairwise distinct); indices are int32.
    const int* fi = 0; const float* fv = 0;
    const int* ei = 0; const float* ew = 0;
    const float *W1 = 0, *b1 = 0, *W2 = 0, *b2 = 0;
    int nnz = 0, ne = 0;
    for (int i = 0; i < n_in; i++) {
        int s = in_sizes[i];
        const void* p = d_in[i];
        if (s == 2 * MAX_NNZ)            { fi = (const int*)p; }
        else if (s == MAX_NNZ)           { fv = (const float*)p; nnz = s; }
        else if (s == 2 * MAX_NE)        { ei = (const int*)p; }
        else if (s == MAX_NE)            { ew = (const float*)p; ne = s; }
        else if (s == N_FEATS * HID)     { W1 = (const float*)p; }
        else if (s == HID)               { b1 = (const float*)p; }
        else if (s == HID * NLAB)        { W2 = (const float*)p; }
        else if (s == NLAB)              { b2 = (const float*)p; }
    }
    float* out = (float*)d_out;
    int tot = nnz + ne;

    // CSR build (g_cnt arrives all-zero: first call by static init, later calls
    // restored by k_feat_csr / k_edge40_lsm of the previous call)
    k_hist<<<(tot + 255) / 256, 256>>>(fi, nnz, ei, ne, W1);
    k_scan<<<250, 800>>>();
    k_scat<<<(tot + 255) / 256, 256>>>(fi, fv, nnz, ei, ew, ne);

    // GCN forward (gather-only, no atomics)
    k_feat_csr<<<(N_NODES + 31) / 32, 256>>>(b1);
    k_edge64_csr<<<(N_NODES + 31) / 32, 256>>>();
    k_dense<<<(N_NODES + 255) / 256, 256>>>(W2, b2);
    k_edge40_lsm<<<(N_NODES + 31) / 32, 256>>>(out);
}

// round 15
// speedup vs baseline: 1.0578x; 1.0578x over previous
#include <cuda_runtime.h>
#include <cuda_fp16.h>
#include <math.h>

#define N_NODES 100000
#define N_FEATS 2048
#define HID 64
#define NLAB 40
#define N_SEG (2 * N_NODES)
#define MAX_NNZ 2500000
#define MAX_NE  1700000

// ---- scratch (static: no allocations; zero-init at load) ----
__device__ __align__(16) __half2 g_W1h[N_FEATS * HID / 2];   // fp16 W1 (256 KB)
__device__ __align__(16) __half2 g_h1h[N_NODES * HID / 2];   // h1 fp16 (12.8 MB)
__device__ __align__(16) __half2 g_h2h[N_NODES * HID / 2];   // h2 fp16, relu'ed
__device__ __align__(16) __half2 g_z1h[N_NODES * NLAB / 2];  // z1 fp16 (8 MB)
__device__ int g_cnt[N_SEG];        // invariant: all-zero at kernel_launch entry
__device__ int g_start[N_SEG];
__device__ int g_cursor[N_SEG];
__device__ int gTotF, gTotE;        // scan bases; reset by k_dense each call
__device__ unsigned g_fbuf[MAX_NNZ];                  // (col<<16)|fp16(val), by row
__device__ __align__(8) int2 g_ebuf[MAX_NE];          // (col, w bits), by row

__device__ __forceinline__ int clamp_i(int i, int n) {
    i = i < 0 ? 0 : i;
    return i >= n ? n - 1 : i;
}

__device__ __forceinline__ void acc8(float4& a, float4& b, float s, uint4 u) {
    float2 lx = __half22float2(*(__half2*)&u.x);
    float2 ly = __half22float2(*(__half2*)&u.y);
    float2 lz = __half22float2(*(__half2*)&u.z);
    float2 lw = __half22float2(*(__half2*)&u.w);
    a.x += s * lx.x; a.y += s * lx.y; a.z += s * ly.x; a.w += s * ly.y;
    b.x += s * lz.x; b.y += s * lz.y; b.z += s * lw.x; b.w += s * lw.y;
}
__device__ __forceinline__ uint4 f8_to_h8(float4 a, float4 b) {
    __half2 p = __floats2half2_rn(a.x, a.y), q = __floats2half2_rn(a.z, a.w);
    __half2 r = __floats2half2_rn(b.x, b.y), s = __floats2half2_rn(b.z, b.w);
    uint4 u;
    u.x = *(unsigned*)&p; u.y = *(unsigned*)&q;
    u.z = *(unsigned*)&r; u.w = *(unsigned*)&s;
    return u;
}
// fp16 HFMA2 accumulate: acc += v2 * u  (4 HFMA2, no unpack)
__device__ __forceinline__ void hacc8(uint4& a, __half2 v2, uint4 u) {
    *(__half2*)&a.x = __hfma2(v2, *(__half2*)&u.x, *(__half2*)&a.x);
    *(__half2*)&a.y = __hfma2(v2, *(__half2*)&u.y, *(__half2*)&a.y);
    *(__half2*)&a.z = __hfma2(v2, *(__half2*)&u.z, *(__half2*)&a.z);
    *(__half2*)&a.w = __hfma2(v2, *(__half2*)&u.w, *(__half2*)&a.w);
}

// ---------------- build: histogram (+ W1 fp16 convert folded in) ----------------
__global__ void k_hist(const int* __restrict__ fi, int nnz,
                       const int* __restrict__ ei, int ne,
                       const float* __restrict__ W1) {
    int e = blockIdx.x * blockDim.x + threadIdx.x;
    if (e < N_FEATS * HID / 2) {
        float2 f = __ldg((const float2*)W1 + e);
        g_W1h[e] = __floats2half2_rn(f.x, f.y);
    }
    if (e < nnz) {
        atomicAdd(&g_cnt[clamp_i(__ldg(&fi[e]), N_NODES)], 1);
    } else if (e < nnz + ne) {
        int t = e - nnz;
        atomicAdd(&g_cnt[N_NODES + clamp_i(__ldg(&ei[t]), N_NODES)], 1);
    }
}

// ---------------- single-kernel scan: 250 blocks x 800 (125 feat | 125 edge) --------
__global__ __launch_bounds__(800) void k_scan() {
    int tid = threadIdx.x;
    int bid = blockIdx.x;
    int i = bid * 800 + tid;                 // 250*800 = 200000 = N_SEG exactly
    int v = g_cnt[i];
    int lane = tid & 31, wid = tid >> 5;
    int x = v;
#pragma unroll
    for (int o = 1; o < 32; o <<= 1) {
        int y = __shfl_up_sync(0xFFFFFFFFu, x, o);
        if (lane >= o) x += y;
    }
    __shared__ int ws[25];
    __shared__ int sbase;
    if (lane == 31) ws[wid] = x;
    __syncthreads();
    if (tid < 32) {
        int s = (tid < 25) ? ws[tid] : 0;
#pragma unroll
        for (int o = 1; o < 32; o <<= 1) {
            int y = __shfl_up_sync(0xFFFFFFFFu, s, o);
            if (tid >= o) s += y;
        }
        if (tid < 25) ws[tid] = s;           // inclusive scan of warp sums
        if (tid == 24) sbase = atomicAdd((bid >= 125) ? &gTotE : &gTotF, s);
    }
    __syncthreads();
    int incl = x + (wid ? ws[wid - 1] : 0);
    int st = sbase + incl - v;               // exclusive start (fbuf- or ebuf-relative)
    g_start[i] = st;
    g_cursor[i] = st;
}

// ---------------- scatter: features (packed 4B) then edges (8B) ----------------
__global__ void k_scat(const int* __restrict__ fi, const float* __restrict__ fv, int nnz,
                       const int* __restrict__ ei, const float* __restrict__ ew, int ne) {
    int e = blockIdx.x * blockDim.x + threadIdx.x;
    if (e < nnz) {
        int row = clamp_i(__ldg(&fi[e]), N_NODES);
        int col = clamp_i(__ldg(&fi[nnz + e]), N_FEATS);
        __half hv = __float2half_rn(__ldg(&fv[e]));
        int pos = atomicAdd(&g_cursor[row], 1);
        g_fbuf[pos] = ((unsigned)col << 16) | (unsigned)*(unsigned short*)&hv;
    } else if (e < nnz + ne) {
        int t = e - nnz;
        int row = clamp_i(__ldg(&ei[t]), N_NODES);
        int col = clamp_i(__ldg(&ei[ne + t]), N_NODES);
        float wv = __ldg(&ew[t]);
        int pos = atomicAdd(&g_cursor[N_NODES + row], 1);    // ebuf-relative
        g_ebuf[pos] = make_int2(col, __float_as_int(wv));
    }
}

// ---------------- gather-only SpMMs: 8 lanes x uint4(16B) per row, unroll 8 --------
// h1[row] = b1 + sum_i val_i * W1[col_i, :]   (fp16 HFMA2 accumulation)
__global__ __launch_bounds__(256) void k_feat_csr(const float* __restrict__ b1) {
    int tid = threadIdx.x;
    int row = blockIdx.x * 32 + (tid >> 3);
    int q = tid & 7;
    if (row >= N_NODES) return;
    int s = g_start[row];
    int n = g_cnt[row];
    uint4 acc = f8_to_h8(__ldg((const float4*)b1 + q * 2),
                         __ldg((const float4*)b1 + q * 2 + 1));
    const uint4* W = (const uint4*)g_W1h;     // 8 uint4 per W1 row
    int i = 0;
    for (; i + 8 <= n; i += 8) {
        unsigned p[8];
#pragma unroll
        for (int j = 0; j < 8; j++) p[j] = __ldg(&g_fbuf[s + i + j]);
        uint4 u[8];
#pragma unroll
        for (int j = 0; j < 8; j++) u[j] = __ldg(W + (size_t)(p[j] >> 16) * 8 + q);
#pragma unroll
        for (int j = 0; j < 8; j++) {
            unsigned short b = (unsigned short)p[j];
            hacc8(acc, __half2half2(*(__half*)&b), u[j]);
        }
    }
    for (; i < n; i++) {
        unsigned p = __ldg(&g_fbuf[s + i]);
        uint4 u = __ldg(W + (size_t)(p >> 16) * 8 + q);
        unsigned short b = (unsigned short)p;
        hacc8(acc, __half2half2(*(__half*)&b), u);
    }
    ((uint4*)g_h1h)[(size_t)row * 8 + q] = acc;
    if (q == 0) g_cnt[row] = 0;               // restore invariant for next call
}

// h2[row] = relu( sum_i w_i * h1[col_i] )   (fp16 HFMA2 accumulation)
__global__ __launch_bounds__(256) void k_edge64_csr() {
    int tid = threadIdx.x;
    int row = blockIdx.x * 32 + (tid >> 3);
    int q = tid & 7;
    if (row >= N_NODES) return;
    int s = g_start[N_NODES + row];
    int n = g_cnt[N_NODES + row];
    const uint4* H = (const uint4*)g_h1h;
    uint4 acc = make_uint4(0u, 0u, 0u, 0u);   // fp16 zeros
    int i = 0;
    for (; i + 8 <= n; i += 8) {
        int2 p[8];
#pragma unroll
        for (int j = 0; j < 8; j++) p[j] = __ldg(&g_ebuf[s + i + j]);
        uint4 u[8];
#pragma unroll
        for (int j = 0; j < 8; j++) u[j] = __ldg(H + (size_t)p[j].x * 8 + q);
#pragma unroll
        for (int j = 0; j < 8; j++)
            hacc8(acc, __float2half2_rn(__int_as_float(p[j].y)), u[j]);
    }
    for (; i < n; i++) {
        int2 p = __ldg(&g_ebuf[s + i]);
        uint4 u = __ldg(H + (size_t)p.x * 8 + q);
        hacc8(acc, __float2half2_rn(__int_as_float(p.y)), u);
    }
    // relu in fp16
    __half2 z2 = __float2half2_rn(0.f);
    *(__half2*)&acc.x = __hmax2(*(__half2*)&acc.x, z2);
    *(__half2*)&acc.y = __hmax2(*(__half2*)&acc.y, z2);
    *(__half2*)&acc.z = __hmax2(*(__half2*)&acc.z, z2);
    *(__half2*)&acc.w = __hmax2(*(__half2*)&acc.w, z2);
    ((uint4*)g_h2h)[(size_t)row * 8 + q] = acc;
}

// ---------------- dense: z1 = h2 @ W2 + b2 (fp16 in/out, fp32 math) ----------------
#define PADK 68
__global__ __launch_bounds__(256) void k_dense(const float* __restrict__ W2,
                                               const float* __restrict__ b2) {
    if (blockIdx.x == 0 && threadIdx.x == 0) { gTotF = 0; gTotE = 0; }  // reset scan bases
    __shared__ float sW2t[NLAB * PADK];   // [j][k]
    __shared__ float sb2[NLAB];
    int tid = threadIdx.x;
    for (int i = tid; i < HID * NLAB; i += 256) {
        int k = i / NLAB, j = i - k * NLAB;
        sW2t[j * PADK + k] = W2[i];
    }
    if (tid < NLAB) sb2[tid] = b2[tid];
    __syncthreads();

    int j0 = (tid & 3) * 10;
    int n0 = (blockIdx.x * 64 + (tid >> 2)) * 4;

    float acc[4][10];
#pragma unroll
    for (int nn = 0; nn < 4; nn++)
#pragma unroll
        for (int j = 0; j < 10; j++) acc[nn][j] = sb2[j0 + j];

    const uint2* H = (const uint2*)g_h2h;     // 16 uint2 per h2 row
#pragma unroll
    for (int k4 = 0; k4 < HID; k4 += 4) {
        float4 h[4];
#pragma unroll
        for (int nn = 0; nn < 4; nn++) {
            int nd = n0 + nn;
            if (nd < N_NODES) {
                uint2 u = __ldg(H + (size_t)nd * 16 + (k4 >> 2));
                float2 a = __half22float2(*(__half2*)&u.x);
                float2 b = __half22float2(*(__half2*)&u.y);
                h[nn] = make_float4(a.x, a.y, b.x, b.y);
            } else h[nn] = make_float4(0.f, 0.f, 0.f, 0.f);
        }
#pragma unroll
        for (int j = 0; j < 10; j++) {
            float4 wv = *(const float4*)&sW2t[(j0 + j) * PADK + k4];
#pragma unroll
            for (int nn = 0; nn < 4; nn++)
                acc[nn][j] += h[nn].x * wv.x + h[nn].y * wv.y + h[nn].z * wv.z + h[nn].w * wv.w;
        }
    }
    unsigned short* Z = (unsigned short*)g_z1h;
#pragma unroll
    for (int nn = 0; nn < 4; nn++) {
        int nd = n0 + nn;
        if (nd >= N_NODES) break;
        unsigned* zp = (unsigned*)(Z + (size_t)nd * NLAB + j0);
#pragma unroll
        for (int j = 0; j < 10; j += 2) {
            __half2 hp = __floats2half2_rn(acc[nn][j], acc[nn][j + 1]);
            zp[j >> 1] = *(unsigned*)&hp;
        }
    }
}

// ---------------- final propagate + fused log-softmax (8-lane groups, 5 active) --------
__global__ __launch_bounds__(256) void k_edge40_lsm(float* __restrict__ out) {
    int tid = threadIdx.x;
    int row = blockIdx.x * 32 + (tid >> 3);
    int q = tid & 7;
    if (row >= N_NODES) return;
    int s = g_start[N_NODES + row];
    int n = g_cnt[N_NODES + row];
    bool act = (q < 5);
    const uint4* Z = (const uint4*)g_z1h;     // 5 uint4 per z row
    float4 accA = make_float4(0.f, 0.f, 0.f, 0.f);
    float4 accB = make_float4(0.f, 0.f, 0.f, 0.f);
    int i = 0;
    for (; i + 8 <= n; i += 8) {
        int2 p[8];
#pragma unroll
        for (int j = 0; j < 8; j++) p[j] = __ldg(&g_ebuf[s + i + j]);
        if (act) {
            uint4 u[8];
#pragma unroll
            for (int j = 0; j < 8; j++) u[j] = __ldg(Z + (size_t)p[j].x * 5 + q);
#pragma unroll
            for (int j = 0; j < 8; j++)
                acc8(accA, accB, __int_as_float(p[j].y), u[j]);
        }
    }
    for (; i < n; i++) {
        int2 p = __ldg(&g_ebuf[s + i]);
        if (act) {
            uint4 u = __ldg(Z + (size_t)p.x * 5 + q);
            acc8(accA, accB, __int_as_float(p.y), u);
        }
    }
    // log-softmax across the 8-lane group (lanes 0..4 hold the 40 values)
    float m = act ? fmaxf(fmaxf(fmaxf(accA.x, accA.y), fmaxf(accA.z, accA.w)),
                          fmaxf(fmaxf(accB.x, accB.y), fmaxf(accB.z, accB.w))) : -1e30f;
#pragma unroll
    for (int o = 1; o < 8; o <<= 1) m = fmaxf(m, __shfl_xor_sync(0xFFFFFFFFu, m, o, 8));
    float es = act ? (expf(accA.x - m) + expf(accA.y - m) + expf(accA.z - m) + expf(accA.w - m) +
                      expf(accB.x - m) + expf(accB.y - m) + expf(accB.z - m) + expf(accB.w - m)) : 0.f;
#pragma unroll
    for (int o = 1; o < 8; o <<= 1) es += __shfl_xor_sync(0xFFFFFFFFu, es, o, 8);
    float l = m + logf(es);
    if (act) {
        float* op = out + (size_t)row * NLAB + q * 8;
        *(float4*)op = make_float4(accA.x - l, accA.y - l, accA.z - l, accA.w - l);
        *(float4*)(op + 4) = make_float4(accB.x - l, accB.y - l, accB.z - l, accB.w - l);
    }
    if (q == 0) g_cnt[N_NODES + row] = 0;     // restore invariant for next call
}

extern "C" void kernel_launch(void* const* d_in, const int* in_sizes, int n_in,
                              void* d_out, int out_size) {
    // Bind inputs by element count (pairwise distinct); indices are int32.
    const int* fi = 0; const float* fv = 0;
    const int* ei = 0; const float* ew = 0;
    const float *W1 = 0, *b1 = 0, *W2 = 0, *b2 = 0;
    int nnz = 0, ne = 0;
    for (int i = 0; i < n_in; i++) {
        int s = in_sizes[i];
        const void* p = d_in[i];
        if (s == 2 * MAX_NNZ)            { fi = (const int*)p; }
        else if (s == MAX_NNZ)           { fv = (const float*)p; nnz = s; }
        else if (s == 2 * MAX_NE)        { ei = (const int*)p; }
        else if (s == MAX_NE)            { ew = (const float*)p; ne = s; }
        else if (s == N_FEATS * HID)     { W1 = (const float*)p; }
        else if (s == HID)               { b1 = (const float*)p; }
        else if (s == HID * NLAB)        { W2 = (const float*)p; }
        else if (s == NLAB)              { b2 = (const float*)p; }
    }
    float* out = (float*)d_out;
    int tot = nnz + ne;

    // CSR build (g_cnt arrives all-zero: first call by static init, later calls
    // restored by k_feat_csr / k_edge40_lsm of the previous call)
    k_hist<<<(tot + 255) / 256, 256>>>(fi, nnz, ei, ne, W1);
    k_scan<<<250, 800>>>();
    k_scat<<<(tot + 255) / 256, 256>>>(fi, fv, nnz, ei, ew, ne);

    // GCN forward (gather-only, no atomics)
    k_feat_csr<<<(N_NODES + 31) / 32, 256>>>(b1);
    k_edge64_csr<<<(N_NODES + 31) / 32, 256>>>();
    k_dense<<<(N_NODES + 255) / 256, 256>>>(W2, b2);
    k_edge40_lsm<<<(N_NODES + 31) / 32, 256>>>(out);
}